// round 3
// baseline (speedup 1.0000x reference)
#include <cuda_runtime.h>
#include <cstdint>
#include <cstddef>

// Xonv2D: out[b,o,h,w] = sum_{c,kh,kw} x[b,c,h+kh-1,w+kw-1] * W[h,w,o,c,kh,kw] + bias[h,w,o]
// B=4, CIN=COUT=16, K=3, H=W=128.  Weights = 151MB streamed once -> HBM-bound.
// Persistent CTAs, 3-deep TMA ring for weights, x halo tile staged in smem
// (float4 over batch, XOR-swizzled), all 4 batches per thread.

static constexpr int Hc = 128, Wc = 128;
static constexpr int GROUPS = 4096;                      // 4-pixel groups
static constexpr int RING = 3;
static constexpr int FLOATS_PER_PX = 16 * 16 * 9;        // 2304
static constexpr int CHUNK_FLOATS  = 4 * FLOATS_PER_PX;  // 9216
static constexpr int CHUNK_BYTES   = CHUNK_FLOATS * 4;   // 36864
static constexpr int XTILE_FLOATS  = 16 * 3 * 6 * 4;     // c*r*col*b = 1152
static constexpr int SMEM_X_OFF    = RING * CHUNK_BYTES;          // 110592
static constexpr int SMEM_MBAR_OFF = SMEM_X_OFF + XTILE_FLOATS*4; // 115200
static constexpr int SMEM_TOTAL    = SMEM_MBAR_OFF + RING * 8 + 8;
static constexpr int GRID          = 304;

__device__ __forceinline__ uint32_t smem_u32(const void* p) {
    return (uint32_t)__cvta_generic_to_shared(p);
}
__device__ __forceinline__ void mbar_init(uint32_t a, uint32_t count) {
    asm volatile("mbarrier.init.shared.b64 [%0], %1;" :: "r"(a), "r"(count) : "memory");
}
__device__ __forceinline__ void mbar_expect_tx(uint32_t a, uint32_t bytes) {
    asm volatile("mbarrier.arrive.expect_tx.shared.b64 _, [%0], %1;" :: "r"(a), "r"(bytes) : "memory");
}
__device__ __forceinline__ void tma_bulk_g2s(uint32_t dst, const void* src, uint32_t bytes, uint32_t mbar) {
    asm volatile("cp.async.bulk.shared::cta.global.mbarrier::complete_tx::bytes [%0], [%1], %2, [%3];"
                 :: "r"(dst), "l"(src), "r"(bytes), "r"(mbar) : "memory");
}
__device__ __forceinline__ void mbar_wait(uint32_t a, uint32_t parity) {
    uint32_t done;
    asm volatile(
        "{\n\t.reg .pred p;\n\t"
        "mbarrier.try_wait.parity.acquire.cta.shared::cta.b64 p, [%1], %2;\n\t"
        "selp.b32 %0, 1, 0, p;\n\t}"
        : "=r"(done) : "r"(a), "r"(parity) : "memory");
    while (!done) {
        asm volatile(
            "{\n\t.reg .pred p;\n\t"
            "mbarrier.try_wait.parity.acquire.cta.shared::cta.b64 p, [%1], %2, 0x989680;\n\t"
            "selp.b32 %0, 1, 0, p;\n\t}"
            : "=r"(done) : "r"(a), "r"(parity) : "memory");
    }
}

__global__ void __launch_bounds__(128, 2)
xonv2d_kernel(const float* __restrict__ x,
              const float* __restrict__ wts,
              const float* __restrict__ bias,
              float* __restrict__ out)
{
    extern __shared__ char smem[];
    float*  swt = reinterpret_cast<float*>(smem);
    float*  sx  = reinterpret_cast<float*>(smem + SMEM_X_OFF);
    float4* sx4 = reinterpret_cast<float4*>(smem + SMEM_X_OFF);
    const uint32_t mb = smem_u32(smem + SMEM_MBAR_OFF);

    const int t   = threadIdx.x;
    const int bid = blockIdx.x;

    if (t == 0) {
        #pragma unroll
        for (int s = 0; s < RING; s++) mbar_init(mb + s * 8, 1);
    }
    __syncthreads();

    // Prologue: fill slots 0,1 (chunks bid, bid+GRID).
    if (t == 0) {
        #pragma unroll
        for (int j = 0; j < RING - 1; j++) {
            int gi = bid + j * GRID;
            if (gi < GROUPS) {
                mbar_expect_tx(mb + j * 8, CHUNK_BYTES);
                tma_bulk_g2s(smem_u32(swt + j * CHUNK_FLOATS),
                             wts + (size_t)gi * CHUNK_FLOATS, CHUNK_BYTES, mb + j * 8);
            }
        }
    }

    // Thread decomposition: og (bits0-2) = cout pair, jh (bits3-4) = cin quarter,
    // px (bits5-6) = pixel in group. Each thread: 2 couts x 4 cins x 9 taps x 4 batches.
    const int og = t & 7;
    const int jh = (t >> 3) & 3;
    const int px = t >> 5;

    for (int j = 0, gi = bid; gi < GROUPS; j++, gi += GRID) {
        const int slot   = j % RING;
        const int parity = (j / RING) & 1;

        __syncthreads();   // prior iter done reading sx and weight slot (j-1)

        // Issue TMA for chunk j+2 into the slot chunk j-1 just freed.
        if (t == 0) {
            int gn = gi + (RING - 1) * GRID;
            if (gn < GROUPS) {
                int sn = (j + RING - 1) % RING;
                mbar_expect_tx(mb + sn * 8, CHUNK_BYTES);
                tma_bulk_g2s(smem_u32(swt + sn * CHUNK_FLOATS),
                             wts + (size_t)gn * CHUNK_FLOATS, CHUNK_BYTES, mb + sn * 8);
            }
        }

        const int pix0 = gi * 4;
        const int h0   = pix0 >> 7;
        const int w0   = pix0 & 127;

        // ---- x halo tile fill: sx word[c*18 + r*6 + col] ^ ((c>>2)&3) holds float4 over b.
        // 1152 floats = 9 per thread; consecutive lanes -> mostly consecutive ww (coalesced).
        #pragma unroll
        for (int it = 0; it < 9; it++) {
            const int i  = t + it * 128;
            const int wi = i % 6;
            const int r  = (i / 6) % 3;
            const int c  = (i / 18) % 16;
            const int b  = i / 288;
            const int hh = h0 - 1 + r;
            const int ww = w0 - 1 + wi;
            float v = 0.0f;
            if (hh >= 0 && hh < Hc && ww >= 0 && ww < Wc)
                v = __ldg(x + (((size_t)(b * 16 + c)) * Hc + hh) * Wc + ww);
            const int word = (c * 18 + r * 6 + wi) ^ ((c >> 2) & 3);
            sx[word * 4 + b] = v;
        }
        __syncthreads();             // sx tile complete
        mbar_wait(mb + slot * 8, parity);  // weights ready

        const float4* wb4 = reinterpret_cast<const float4*>(swt) +
                            (slot * 2304 + px * 576 + og * 72 + jh * 9);
        const int xbase = jh * 72 + px;     // + dc*18 + r*6 + s, then ^jh

        float acc[2][4];
        #pragma unroll
        for (int oo = 0; oo < 2; oo++)
            #pragma unroll
            for (int b = 0; b < 4; b++) acc[oo][b] = 0.0f;

        #pragma unroll
        for (int i4 = 0; i4 < 9; i4++) {
            const float4 wv0 = wb4[i4];        // cout o0 = og*2
            const float4 wv1 = wb4[36 + i4];   // cout o1 = og*2+1
            #pragma unroll
            for (int k = 0; k < 4; k++) {
                const int jj = i4 * 4 + k;     // 0..35 within jh quarter
                const int dc = jj / 9;
                const int rs = jj % 9;
                const int r  = rs / 3;
                const int s  = rs % 3;
                const float4 xv = sx4[(xbase + dc * 18 + r * 6 + s) ^ jh];
                const float w0f = (k == 0) ? wv0.x : (k == 1) ? wv0.y : (k == 2) ? wv0.z : wv0.w;
                const float w1f = (k == 0) ? wv1.x : (k == 1) ? wv1.y : (k == 2) ? wv1.z : wv1.w;
                acc[0][0] += w0f * xv.x;  acc[0][1] += w0f * xv.y;
                acc[0][2] += w0f * xv.z;  acc[0][3] += w0f * xv.w;
                acc[1][0] += w1f * xv.x;  acc[1][1] += w1f * xv.y;
                acc[1][2] += w1f * xv.z;  acc[1][3] += w1f * xv.w;
            }
        }

        // Reduce the 4 jh quarters (lane bits 3,4).
        #pragma unroll
        for (int oo = 0; oo < 2; oo++)
            #pragma unroll
            for (int b = 0; b < 4; b++) {
                float v = acc[oo][b];
                v += __shfl_xor_sync(0xffffffffu, v, 8);
                v += __shfl_xor_sync(0xffffffffu, v, 16);
                acc[oo][b] = v;
            }

        if (jh == 0) {
            const int pix = pix0 + px;
            const int h   = pix >> 7;
            const int w   = pix & 127;
            const float2 bv = *reinterpret_cast<const float2*>(bias + (size_t)pix * 16 + og * 2);
            #pragma unroll
            for (int oo = 0; oo < 2; oo++) {
                const int o = og * 2 + oo;
                const float bs = oo ? bv.y : bv.x;
                #pragma unroll
                for (int b = 0; b < 4; b++)
                    out[(((size_t)(b * 16 + o)) * Hc + h) * Wc + w] = acc[oo][b] + bs;
            }
        }
    }
}

extern "C" void kernel_launch(void* const* d_in, const int* in_sizes, int n_in,
                              void* d_out, int out_size) {
    const float* x    = (const float*)d_in[0];
    const float* wts  = (const float*)d_in[1];
    const float* bias = (const float*)d_in[2];
    float* out        = (float*)d_out;

    cudaFuncSetAttribute(xonv2d_kernel, cudaFuncAttributeMaxDynamicSharedMemorySize, SMEM_TOTAL);
    xonv2d_kernel<<<GRID, 128, SMEM_TOTAL>>>(x, wts, bias, out);
}

// round 4
// speedup vs baseline: 1.4410x; 1.4410x over previous
#include <cuda_runtime.h>
#include <cstdint>
#include <cstddef>

// Xonv2D: out[b,o,h,w] = sum_{c,kh,kw} x[b,c,h+kh-1,w+kw-1] * W[h,w,o,c,kh,kw] + bias[h,w,o]
// B=4, CIN=COUT=16, K=3, H=W=128.  Weights = 151MB streamed once -> HBM-bound.
// Persistent CTAs, 3-deep TMA ring for weights.  x halo tile in smem (float4 over
// batch, ^jh swizzle), x fill software-pipelined via register prefetch.
// Cout mapping o = oo*8+og makes weight LDS.128 exactly conflict-free (4 phases).

static constexpr int Hc = 128, Wc = 128;
static constexpr int GROUPS = 4096;                      // 4-pixel groups
static constexpr int RING = 3;
static constexpr int FLOATS_PER_PX = 16 * 16 * 9;        // 2304
static constexpr int CHUNK_FLOATS  = 4 * FLOATS_PER_PX;  // 9216
static constexpr int CHUNK_BYTES   = CHUNK_FLOATS * 4;   // 36864
static constexpr int XTILE_FLOATS  = 16 * 3 * 6 * 4;     // 1152
static constexpr int SMEM_X_OFF    = RING * CHUNK_BYTES;            // 110592
static constexpr int SMEM_MBAR_OFF = SMEM_X_OFF + XTILE_FLOATS * 4; // 115200
static constexpr int SMEM_TOTAL    = SMEM_MBAR_OFF + RING * 8 + 8;
static constexpr int GRID          = 304;

__device__ __forceinline__ uint32_t smem_u32(const void* p) {
    return (uint32_t)__cvta_generic_to_shared(p);
}
__device__ __forceinline__ void mbar_init(uint32_t a, uint32_t count) {
    asm volatile("mbarrier.init.shared.b64 [%0], %1;" :: "r"(a), "r"(count) : "memory");
}
__device__ __forceinline__ void mbar_expect_tx(uint32_t a, uint32_t bytes) {
    asm volatile("mbarrier.arrive.expect_tx.shared.b64 _, [%0], %1;" :: "r"(a), "r"(bytes) : "memory");
}
__device__ __forceinline__ void tma_bulk_g2s(uint32_t dst, const void* src, uint32_t bytes, uint32_t mbar) {
    asm volatile("cp.async.bulk.shared::cta.global.mbarrier::complete_tx::bytes [%0], [%1], %2, [%3];"
                 :: "r"(dst), "l"(src), "r"(bytes), "r"(mbar) : "memory");
}
__device__ __forceinline__ void mbar_wait(uint32_t a, uint32_t parity) {
    uint32_t done;
    asm volatile(
        "{\n\t.reg .pred p;\n\t"
        "mbarrier.try_wait.parity.acquire.cta.shared::cta.b64 p, [%1], %2;\n\t"
        "selp.b32 %0, 1, 0, p;\n\t}"
        : "=r"(done) : "r"(a), "r"(parity) : "memory");
    while (!done) {
        asm volatile(
            "{\n\t.reg .pred p;\n\t"
            "mbarrier.try_wait.parity.acquire.cta.shared::cta.b64 p, [%1], %2, 0x989680;\n\t"
            "selp.b32 %0, 1, 0, p;\n\t}"
            : "=r"(done) : "r"(a), "r"(parity) : "memory");
    }
}

__global__ void __launch_bounds__(128, 2)
xonv2d_kernel(const float* __restrict__ x,
              const float* __restrict__ wts,
              const float* __restrict__ bias,
              float* __restrict__ out)
{
    extern __shared__ char smem[];
    float*  swt = reinterpret_cast<float*>(smem);
    float*  sx  = reinterpret_cast<float*>(smem + SMEM_X_OFF);
    float4* sx4 = reinterpret_cast<float4*>(smem + SMEM_X_OFF);
    const uint32_t mb = smem_u32(smem + SMEM_MBAR_OFF);

    const int t   = threadIdx.x;
    const int bid = blockIdx.x;

    if (t == 0) {
        #pragma unroll
        for (int s = 0; s < RING; s++) mbar_init(mb + s * 8, 1);
    }
    __syncthreads();

    // Prologue: TMA for weight chunks bid, bid+GRID into slots 0,1.
    if (t == 0) {
        #pragma unroll
        for (int j = 0; j < RING - 1; j++) {
            int gi = bid + j * GRID;
            if (gi < GROUPS) {
                mbar_expect_tx(mb + j * 8, CHUNK_BYTES);
                tma_bulk_g2s(smem_u32(swt + j * CHUNK_FLOATS),
                             wts + (size_t)gi * CHUNK_FLOATS, CHUNK_BYTES, mb + j * 8);
            }
        }
    }

    // Thread decomposition: og (bits0-2) -> couts {og, og+8}; jh (bits3-4) = cin
    // quarter; px (bits5-6) = pixel in group. 2 couts x 4 cins x 9 taps x 4 batches.
    const int og = t & 7;
    const int jh = (t >> 3) & 3;
    const int px = t >> 5;

    // ---- x prefetch for first chunk (9 values/thread, coalesced rows of 6) ----
    float xr[9];
    {
        const int pix0 = bid * 4;
        const int h0 = pix0 >> 7, w0 = pix0 & 127;
        #pragma unroll
        for (int it = 0; it < 9; it++) {
            const int i  = t + it * 128;
            const int wi = i % 6;
            const int r  = (i / 6) % 3;
            const int c  = (i / 18) % 16;
            const int b  = i / 288;
            const int hh = h0 - 1 + r;
            const int ww = w0 - 1 + wi;
            xr[it] = (hh >= 0 && hh < Hc && ww >= 0 && ww < Wc)
                     ? __ldg(x + (((size_t)(b * 16 + c)) * Hc + hh) * Wc + ww) : 0.0f;
        }
    }

    for (int j = 0, gi = bid; gi < GROUPS; j++, gi += GRID) {
        const int slot   = j % RING;
        const int parity = (j / RING) & 1;

        __syncthreads();   // prev iter done reading sx and weight slot (j-1)

        // Store prefetched x into the (single) sx tile.
        #pragma unroll
        for (int it = 0; it < 9; it++) {
            const int i  = t + it * 128;
            const int wi = i % 6;
            const int r  = (i / 6) % 3;
            const int c  = (i / 18) % 16;
            const int b  = i / 288;
            const int word = (c * 18 + r * 6 + wi) ^ ((c >> 2) & 3);
            sx[word * 4 + b] = xr[it];
        }

        // TMA for weight chunk j+2 into the slot chunk j-1 just freed.
        if (t == 0) {
            int gn = gi + (RING - 1) * GRID;
            if (gn < GROUPS) {
                int sn = (j + RING - 1) % RING;
                mbar_expect_tx(mb + sn * 8, CHUNK_BYTES);
                tma_bulk_g2s(smem_u32(swt + sn * CHUNK_FLOATS),
                             wts + (size_t)gn * CHUNK_FLOATS, CHUNK_BYTES, mb + sn * 8);
            }
        }
        __syncthreads();   // sx tile ready

        // Prefetch x for next chunk (hidden behind mbar_wait + compute).
        {
            const int gn2 = gi + GRID;
            if (gn2 < GROUPS) {
                const int pix0n = gn2 * 4;
                const int h0 = pix0n >> 7, w0 = pix0n & 127;
                #pragma unroll
                for (int it = 0; it < 9; it++) {
                    const int i  = t + it * 128;
                    const int wi = i % 6;
                    const int r  = (i / 6) % 3;
                    const int c  = (i / 18) % 16;
                    const int b  = i / 288;
                    const int hh = h0 - 1 + r;
                    const int ww = w0 - 1 + wi;
                    xr[it] = (hh >= 0 && hh < Hc && ww >= 0 && ww < Wc)
                             ? __ldg(x + (((size_t)(b * 16 + c)) * Hc + hh) * Wc + ww) : 0.0f;
                }
            }
        }

        mbar_wait(mb + slot * 8, parity);  // weights for chunk j ready

        // Weight float4 index within pixel block: o*36 + jh*9 + i4 ; o0=og, o1=og+8.
        const float4* wp = reinterpret_cast<const float4*>(swt) +
                           (slot * 2304 + px * 576 + og * 36 + jh * 9);
        const int xb = jh * 72 + px;

        float acc[2][4];
        #pragma unroll
        for (int oo = 0; oo < 2; oo++)
            #pragma unroll
            for (int b = 0; b < 4; b++) acc[oo][b] = 0.0f;

        #pragma unroll
        for (int i4 = 0; i4 < 9; i4++) {
            const float4 wv0 = wp[i4];         // cout og
            const float4 wv1 = wp[288 + i4];   // cout og+8
            #pragma unroll
            for (int k = 0; k < 4; k++) {
                const int jj = i4 * 4 + k;     // 0..35 within jh quarter
                const int dc = jj / 9;
                const int rs = jj % 9;
                const int r  = rs / 3;
                const int s  = rs % 3;
                const float4 xv = sx4[(xb + dc * 18 + r * 6 + s) ^ jh];
                const float w0f = (k == 0) ? wv0.x : (k == 1) ? wv0.y : (k == 2) ? wv0.z : wv0.w;
                const float w1f = (k == 0) ? wv1.x : (k == 1) ? wv1.y : (k == 2) ? wv1.z : wv1.w;
                acc[0][0] += w0f * xv.x;  acc[0][1] += w0f * xv.y;
                acc[0][2] += w0f * xv.z;  acc[0][3] += w0f * xv.w;
                acc[1][0] += w1f * xv.x;  acc[1][1] += w1f * xv.y;
                acc[1][2] += w1f * xv.z;  acc[1][3] += w1f * xv.w;
            }
        }

        // Reduce the 4 jh quarters (lane bits 3,4).
        #pragma unroll
        for (int oo = 0; oo < 2; oo++)
            #pragma unroll
            for (int b = 0; b < 4; b++) {
                float v = acc[oo][b];
                v += __shfl_xor_sync(0xffffffffu, v, 8);
                v += __shfl_xor_sync(0xffffffffu, v, 16);
                acc[oo][b] = v;
            }

        if (jh == 0) {
            const int pix = gi * 4 + px;
            const int h   = pix >> 7;
            const int w   = pix & 127;
            const float b0 = __ldg(bias + (size_t)pix * 16 + og);
            const float b1 = __ldg(bias + (size_t)pix * 16 + og + 8);
            #pragma unroll
            for (int b = 0; b < 4; b++) {
                out[(((size_t)(b * 16 + og))     * Hc + h) * Wc + w] = acc[0][b] + b0;
                out[(((size_t)(b * 16 + og + 8)) * Hc + h) * Wc + w] = acc[1][b] + b1;
            }
        }
    }
}

extern "C" void kernel_launch(void* const* d_in, const int* in_sizes, int n_in,
                              void* d_out, int out_size) {
    const float* x    = (const float*)d_in[0];
    const float* wts  = (const float*)d_in[1];
    const float* bias = (const float*)d_in[2];
    float* out        = (float*)d_out;

    cudaFuncSetAttribute(xonv2d_kernel, cudaFuncAttributeMaxDynamicSharedMemorySize, SMEM_TOTAL);
    xonv2d_kernel<<<GRID, 128, SMEM_TOTAL>>>(x, wts, bias, out);
}

// round 5
// speedup vs baseline: 1.8024x; 1.2508x over previous
#include <cuda_runtime.h>
#include <cstdint>
#include <cstddef>

// Xonv2D: out[b,o,h,w] = sum_{c,kh,kw} x[b,c,h+kh-1,w+kw-1] * W[h,w,o,c,kh,kw] + bias[h,w,o]
// B=4, CIN=COUT=16, K=3, H=W=128. Weights = 151MB streamed once -> HBM-bound.
// Persistent CTAs (304 = 2/SM), 256 threads, 3-deep TMA weight ring, x halo tile
// in smem (float4 over batch, xor bank swizzle), x fill register-pipelined,
// coalesced float4 output via smem transpose staging (overlaid on x tile).

static constexpr int Hc = 128, Wc = 128;
static constexpr int GROUPS = 4096;                      // 4-pixel groups
static constexpr int RING = 3;
static constexpr int FLOATS_PER_PX = 16 * 16 * 9;        // 2304
static constexpr int CHUNK_FLOATS  = 4 * FLOATS_PER_PX;  // 9216
static constexpr int CHUNK_BYTES   = CHUNK_FLOATS * 4;   // 36864
static constexpr int XTILE_FLOATS  = 16 * 3 * 6 * 4;     // 1152 (sout 256 floats overlaid)
static constexpr int SMEM_X_OFF    = RING * CHUNK_BYTES;            // 110592
static constexpr int SMEM_MBAR_OFF = SMEM_X_OFF + XTILE_FLOATS * 4; // 115200
static constexpr int SMEM_TOTAL    = SMEM_MBAR_OFF + RING * 8 + 8;  // 115232
static constexpr int GRID          = 304;
static constexpr int NT            = 256;

__device__ __forceinline__ uint32_t smem_u32(const void* p) {
    return (uint32_t)__cvta_generic_to_shared(p);
}
__device__ __forceinline__ void mbar_init(uint32_t a, uint32_t count) {
    asm volatile("mbarrier.init.shared.b64 [%0], %1;" :: "r"(a), "r"(count) : "memory");
}
__device__ __forceinline__ void mbar_expect_tx(uint32_t a, uint32_t bytes) {
    asm volatile("mbarrier.arrive.expect_tx.shared.b64 _, [%0], %1;" :: "r"(a), "r"(bytes) : "memory");
}
__device__ __forceinline__ void tma_bulk_g2s(uint32_t dst, const void* src, uint32_t bytes, uint32_t mbar) {
    asm volatile("cp.async.bulk.shared::cta.global.mbarrier::complete_tx::bytes [%0], [%1], %2, [%3];"
                 :: "r"(dst), "l"(src), "r"(bytes), "r"(mbar) : "memory");
}
__device__ __forceinline__ void mbar_wait(uint32_t a, uint32_t parity) {
    uint32_t done;
    asm volatile(
        "{\n\t.reg .pred p;\n\t"
        "mbarrier.try_wait.parity.acquire.cta.shared::cta.b64 p, [%1], %2;\n\t"
        "selp.b32 %0, 1, 0, p;\n\t}"
        : "=r"(done) : "r"(a), "r"(parity) : "memory");
    while (!done) {
        asm volatile(
            "{\n\t.reg .pred p;\n\t"
            "mbarrier.try_wait.parity.acquire.cta.shared::cta.b64 p, [%1], %2, 0x989680;\n\t"
            "selp.b32 %0, 1, 0, p;\n\t}"
            : "=r"(done) : "r"(a), "r"(parity) : "memory");
    }
}

__global__ void __launch_bounds__(NT, 2)
xonv2d_kernel(const float* __restrict__ x,
              const float* __restrict__ wts,
              const float* __restrict__ bias,
              float* __restrict__ out)
{
    extern __shared__ char smem[];
    float*  swt = reinterpret_cast<float*>(smem);
    float*  sx  = reinterpret_cast<float*>(smem + SMEM_X_OFF);
    float4* sx4 = reinterpret_cast<float4*>(smem + SMEM_X_OFF);
    const uint32_t mb = smem_u32(smem + SMEM_MBAR_OFF);

    const int t   = threadIdx.x;
    const int bid = blockIdx.x;

    if (t == 0) {
        #pragma unroll
        for (int s = 0; s < RING; s++) mbar_init(mb + s * 8, 1);
    }
    __syncthreads();

    // Prologue: TMA weight chunks bid, bid+GRID into slots 0,1.
    if (t == 0) {
        #pragma unroll
        for (int j = 0; j < RING - 1; j++) {
            int gi = bid + j * GRID;
            if (gi < GROUPS) {
                mbar_expect_tx(mb + j * 8, CHUNK_BYTES);
                tma_bulk_g2s(smem_u32(swt + j * CHUNK_FLOATS),
                             wts + (size_t)gi * CHUNK_FLOATS, CHUNK_BYTES, mb + j * 8);
            }
        }
    }

    // Lane mapping: o0l=bit0, ch=bits1-3 (cin pair), o0h=bit4. Warp: o0m=bit5, px=bits6-7.
    // Thread: couts {o0, o0+8} x cins {2ch, 2ch+1} x 9 taps x 4 batches = 144 FMA.
    const int o0  = (t & 1) + 2 * ((t >> 4) & 1) + 4 * ((t >> 5) & 1);
    const int ch  = (t >> 1) & 7;
    const int px  = (t >> 6) & 3;
    const int xsw = (ch >> 1) & 3;

    // ---- x prefetch for first chunk (5 strided loads/thread, coalesced rows) ----
    float xr[5];
    {
        const int pix0 = bid * 4;
        const int h0 = pix0 >> 7, w0 = pix0 & 127;
        #pragma unroll
        for (int it = 0; it < 5; it++) {
            const int i = t + it * NT;
            if (i < XTILE_FLOATS) {
                const int wi = i % 6;
                const int r  = (i / 6) % 3;
                const int c  = (i / 18) % 16;
                const int b  = i / 288;
                const int hh = h0 - 1 + r;
                const int ww = w0 - 1 + wi;
                xr[it] = (hh >= 0 && hh < Hc && ww >= 0 && ww < Wc)
                         ? __ldg(x + (((size_t)(b * 16 + c)) * Hc + hh) * Wc + ww) : 0.0f;
            }
        }
    }

    for (int j = 0, gi = bid; gi < GROUPS; j++, gi += GRID) {
        const int slot   = j % RING;
        const int parity = (j / RING) & 1;

        __syncthreads();   // S1: prev sout-read + sx-read done -> sx writable

        // Store prefetched x: word (c*18 + r*6 + wi) ^ ((c>>2)&3), float4 over b.
        #pragma unroll
        for (int it = 0; it < 5; it++) {
            const int i = t + it * NT;
            if (i < XTILE_FLOATS) {
                const int wi = i % 6;
                const int r  = (i / 6) % 3;
                const int c  = (i / 18) % 16;
                const int b  = i / 288;
                const int word = (c * 18 + r * 6 + wi) ^ ((c >> 2) & 3);
                sx[word * 4 + b] = xr[it];
            }
        }

        // TMA for chunk j+2 into the slot chunk j-1 freed at S1.
        if (t == 0) {
            int gn = gi + (RING - 1) * GRID;
            if (gn < GROUPS) {
                int sn = (j + RING - 1) % RING;
                mbar_expect_tx(mb + sn * 8, CHUNK_BYTES);
                tma_bulk_g2s(smem_u32(swt + sn * CHUNK_FLOATS),
                             wts + (size_t)gn * CHUNK_FLOATS, CHUNK_BYTES, mb + sn * 8);
            }
        }
        __syncthreads();   // S2: sx tile ready

        // Prefetch x for next chunk (consumed next iteration).
        {
            const int gn2 = gi + GRID;
            if (gn2 < GROUPS) {
                const int pix0n = gn2 * 4;
                const int h0 = pix0n >> 7, w0 = pix0n & 127;
                #pragma unroll
                for (int it = 0; it < 5; it++) {
                    const int i = t + it * NT;
                    if (i < XTILE_FLOATS) {
                        const int wi = i % 6;
                        const int r  = (i / 6) % 3;
                        const int c  = (i / 18) % 16;
                        const int b  = i / 288;
                        const int hh = h0 - 1 + r;
                        const int ww = w0 - 1 + wi;
                        xr[it] = (hh >= 0 && hh < Hc && ww >= 0 && ww < Wc)
                                 ? __ldg(x + (((size_t)(b * 16 + c)) * Hc + hh) * Wc + ww) : 0.0f;
                    }
                }
            }
        }

        mbar_wait(mb + slot * 8, parity);  // weights for chunk j ready

        // Weight float2 base: floats [px][o][cin][tap]; cin-pair = 18 contiguous floats.
        const float2* wp = reinterpret_cast<const float2*>(
            swt + slot * CHUNK_FLOATS + px * FLOATS_PER_PX + o0 * 144) + ch * 9;
        const int xb0 = (2 * ch) * 18 + px;   // cc=0 base (+ r*6 + s, then ^xsw)
        const int xb1 = xb0 + 18;             // cc=1

        float a00 = 0.f, a01 = 0.f, a02 = 0.f, a03 = 0.f;
        float a10 = 0.f, a11 = 0.f, a12 = 0.f, a13 = 0.f;

        #pragma unroll
        for (int k = 0; k < 9; k++) {
            const float2 w0 = wp[k];          // cout o0
            const float2 w1 = wp[k + 576];    // cout o0+8 (offset 8*144 floats)
            #pragma unroll
            for (int e = 0; e < 2; e++) {
                const int f   = 2 * k + e;    // 0..17
                const int cc  = f / 9;
                const int tap = f % 9;
                const int r   = tap / 3;
                const int s   = tap % 3;
                const float4 xv = sx4[((cc ? xb1 : xb0) + r * 6 + s) ^ xsw];
                const float wa = e ? w0.y : w0.x;
                const float wb = e ? w1.y : w1.x;
                a00 += wa * xv.x;  a01 += wa * xv.y;  a02 += wa * xv.z;  a03 += wa * xv.w;
                a10 += wb * xv.x;  a11 += wb * xv.y;  a12 += wb * xv.z;  a13 += wb * xv.w;
            }
        }

        // Reduce over ch (lane bits 1-3): 3 butterflies.
        #pragma unroll
        for (int m = 2; m <= 8; m <<= 1) {
            a00 += __shfl_xor_sync(0xffffffffu, a00, m);
            a01 += __shfl_xor_sync(0xffffffffu, a01, m);
            a02 += __shfl_xor_sync(0xffffffffu, a02, m);
            a03 += __shfl_xor_sync(0xffffffffu, a03, m);
            a10 += __shfl_xor_sync(0xffffffffu, a10, m);
            a11 += __shfl_xor_sync(0xffffffffu, a11, m);
            a12 += __shfl_xor_sync(0xffffffffu, a12, m);
            a13 += __shfl_xor_sync(0xffffffffu, a13, m);
        }

        __syncthreads();   // S3: all sx reads done -> sout (overlaid on sx) writable

        // Stage outputs: sout[(b*16+o)*4 + px], written by ch==0 lanes (1 phase).
        if (ch == 0) {
            const int o1 = o0 + 8;
            sx[(0 * 16 + o0) * 4 + px] = a00;
            sx[(1 * 16 + o0) * 4 + px] = a01;
            sx[(2 * 16 + o0) * 4 + px] = a02;
            sx[(3 * 16 + o0) * 4 + px] = a03;
            sx[(0 * 16 + o1) * 4 + px] = a10;
            sx[(1 * 16 + o1) * 4 + px] = a11;
            sx[(2 * 16 + o1) * 4 + px] = a12;
            sx[(3 * 16 + o1) * 4 + px] = a13;
        }
        __syncthreads();   // S4: sout ready

        // Coalesced write: thread t<64 -> (b = t>>4, o = t&15), float4 over 4 pixels.
        if (t < 64) {
            const int pix0 = gi * 4;
            float4 v = sx4[t];
            const int o = t & 15;
            v.x += __ldg(bias + (size_t)(pix0 + 0) * 16 + o);
            v.y += __ldg(bias + (size_t)(pix0 + 1) * 16 + o);
            v.z += __ldg(bias + (size_t)(pix0 + 2) * 16 + o);
            v.w += __ldg(bias + (size_t)(pix0 + 3) * 16 + o);
            *reinterpret_cast<float4*>(out + (size_t)t * (Hc * Wc) + pix0) = v;
        }
    }
}

extern "C" void kernel_launch(void* const* d_in, const int* in_sizes, int n_in,
                              void* d_out, int out_size) {
    const float* x    = (const float*)d_in[0];
    const float* wts  = (const float*)d_in[1];
    const float* bias = (const float*)d_in[2];
    float* out        = (float*)d_out;

    cudaFuncSetAttribute(xonv2d_kernel, cudaFuncAttributeMaxDynamicSharedMemorySize, SMEM_TOTAL);
    xonv2d_kernel<<<GRID, NT, SMEM_TOTAL>>>(x, wts, bias, out);
}